// round 12
// baseline (speedup 1.0000x reference)
#include <cuda_runtime.h>

// Problem constants
#define TOK_TOTAL 4096      // B_SZ * L = 2 * 2048
#define Dm        1024
#define TPB       256
#define TOKS      2                       // tokens per block
#define NBLK      (TOK_TOTAL / TOKS)      // 2048 blocks
#define OUT_F4_PER_TOK 8196               // (2*1024+1)*16/4

// Reciprocal-A scratch: [1024][16] floats as 4096 float4 (64 KB)
__device__ float4 g_rA4[Dm * 16 / 4];

__device__ __forceinline__ float softplus_f(float v) {
    // matches jax.nn.softplus = max(x,0) + log1p(exp(-|x|))
    return fmaxf(v, 0.0f) + log1pf(__expf(-fabsf(v)));
}

// ---------------------------------------------------------------------------
// Kernel 0: precompute 1/A (full-precision divide; 16K elements, ~2 us)
// ---------------------------------------------------------------------------
__global__ void __launch_bounds__(TPB) ssm_rcp_kernel(const float* __restrict__ A)
{
    const int i = blockIdx.x * TPB + threadIdx.x;   // 0..4095
    const float4 a = __ldg((const float4*)A + i);
    g_rA4[i] = make_float4(1.0f / a.x, 1.0f / a.y, 1.0f / a.z, 1.0f / a.w);
}

// ---------------------------------------------------------------------------
// Kernel 1: fused proj + expansion (R10 structure, divide-free store loop)
// ---------------------------------------------------------------------------
__global__ void __launch_bounds__(TPB, 5) ssm_fused_kernel(
    const float* __restrict__ x,
    const float* __restrict__ Wb,
    const float* __restrict__ Wc,
    const float* __restrict__ Wd,
    const float* __restrict__ A,
    const float* __restrict__ dp,
    float* __restrict__ out)
{
    // All shared arrays vector-typed: alignment guaranteed by the type system.
    __shared__ float4 s_x[TOKS][Dm / 4];   // 8 KB: 2 x rows
    __shared__ float2 s_dx[TOKS][Dm];      // 16 KB: (Delta, x) per (token, d)
    __shared__ float4 s_pj4[TOKS][9];      // [2][36] floats: B(0..15) C(16..31) sdel(32)

    float* s_pjf = (float*)s_pj4;          // row t at float offset t*36 (144 B, aligned)

    const int tid  = threadIdx.x;
    const int bt   = blockIdx.x;
    const int lane = tid & 31;
    const int w    = tid >> 5;

    const float4* A4 = (const float4*)A;

    // ---- Warm A / rA first lines into L1/L2 overlapped with the FMA prologue ----
    float4 a_pre  = __ldg(A4 + tid);
    float4 ra_pre = __ldg(&g_rA4[tid]);

    // ---- Stage 2 x rows (8 KB) ----
    const float4* x4 = (const float4*)x + (size_t)bt * (TOKS * Dm / 4);
    #pragma unroll
    for (int t = 0; t < TOKS; ++t)
        s_x[t][tid] = __ldg(x4 + t * 256 + tid);
    const float4 dpv = __ldg((const float4*)dp + tid);
    __syncthreads();

    // ---- Projections: 33 dots x 2 tokens. Warp w owns cols {w, w+8, ...} ----
    for (int c = w; c < 33; c += 8) {
        const float* Wrow = (c < 16) ? (Wb + c * Dm)
                          : (c < 32) ? (Wc + (c - 16) * Dm)
                          : Wd;
        const float4* W4 = (const float4*)Wrow;
        float acc0 = 0.0f, acc1 = 0.0f;
        #pragma unroll
        for (int k = 0; k < 8; ++k) {
            float4 wv = __ldg(W4 + lane + 32 * k);   // L1-resident across blocks
            float4 x0 = s_x[0][lane + 32 * k];
            float4 x1 = s_x[1][lane + 32 * k];
            acc0 = fmaf(x0.x, wv.x, acc0); acc1 = fmaf(x1.x, wv.x, acc1);
            acc0 = fmaf(x0.y, wv.y, acc0); acc1 = fmaf(x1.y, wv.y, acc1);
            acc0 = fmaf(x0.z, wv.z, acc0); acc1 = fmaf(x1.z, wv.z, acc1);
            acc0 = fmaf(x0.w, wv.w, acc0); acc1 = fmaf(x1.w, wv.w, acc1);
        }
        #pragma unroll
        for (int s = 16; s >= 1; s >>= 1) {
            acc0 += __shfl_xor_sync(0xffffffffu, acc0, s);
            acc1 += __shfl_xor_sync(0xffffffffu, acc1, s);
        }
        if (lane == 0) {
            s_pjf[0 * 36 + c] = acc0;
            s_pjf[1 * 36 + c] = acc1;
        }
    }
    __syncthreads();

    // ---- Softplus once per (token, d); pack (Delta, x) ----
    {
        const int d0 = tid * 4;
        #pragma unroll
        for (int t = 0; t < TOKS; ++t) {
            const float sdel = s_pjf[t * 36 + 32];
            const float4 xv  = s_x[t][tid];
            s_dx[t][d0 + 0] = make_float2(softplus_f(sdel + dpv.x), xv.x);
            s_dx[t][d0 + 1] = make_float2(softplus_f(sdel + dpv.y), xv.y);
            s_dx[t][d0 + 2] = make_float2(softplus_f(sdel + dpv.z), xv.z);
            s_dx[t][d0 + 3] = make_float2(softplus_f(sdel + dpv.w), xv.w);
        }
    }
    __syncthreads();

    float4* out4 = (float4*)out;

    // ---- Per-token expansion: divide-free streaming stores ----
    #pragma unroll
    for (int tt = 0; tt < TOKS; ++tt) {
        const int token = bt * TOKS + tt;
        float4* ob = out4 + (size_t)token * OUT_F4_PER_TOK;
        const float4 Bq = s_pj4[tt][tid & 3];     // per-thread invariant B quad

        #pragma unroll 4
        for (int j = 0; j < 16; ++j) {
            const int f = tid + j * TPB;
            const int d = (tid >> 2) + j * 64;

            const float2 dx = s_dx[tt][d];        // Delta, x — one LDS.64
            const bool first = (tt == 0 && j == 0);
            const float4 a  = first ? a_pre  : __ldg(A4 + f);
            const float4 ra = first ? ra_pre : __ldg(&g_rA4[f]);

            float4 ab;
            ab.x = __expf(dx.x * a.x);
            ab.y = __expf(dx.x * a.y);
            ab.z = __expf(dx.x * a.z);
            ab.w = __expf(dx.x * a.w);

            // deltaB_x = (A_bar-1) * (B*x) / A  =  ab*K - K,  K = B*x*(1/A)
            const float bx0 = Bq.x * dx.y, bx1 = Bq.y * dx.y;
            const float bx2 = Bq.z * dx.y, bx3 = Bq.w * dx.y;
            const float K0 = bx0 * ra.x, K1 = bx1 * ra.y;
            const float K2 = bx2 * ra.z, K3 = bx3 * ra.w;

            float4 o2;
            o2.x = fmaf(ab.x, K0, -K0);
            o2.y = fmaf(ab.y, K1, -K1);
            o2.z = fmaf(ab.z, K2, -K2);
            o2.w = fmaf(ab.w, K3, -K3);

            __stcs(ob + f, ab);            // A_bar plane  [0, 4096)
            __stcs(ob + 4096 + f, o2);     // deltaB_x     [4096, 8192)
        }

        // C row: 16 floats at f4 offset 8192 (s_pj4[tt][4..7])
        if (tid < 4) {
            __stcs(ob + 8192 + tid, s_pj4[tt][4 + tid]);
        }
    }
}

extern "C" void kernel_launch(void* const* d_in, const int* in_sizes, int n_in,
                              void* d_out, int out_size)
{
    const float* x  = (const float*)d_in[0];
    const float* Wb = (const float*)d_in[1];
    const float* Wc = (const float*)d_in[2];
    const float* Wd = (const float*)d_in[3];
    const float* A  = (const float*)d_in[4];
    const float* dp = (const float*)d_in[5];

    ssm_rcp_kernel<<<16, TPB>>>(A);
    ssm_fused_kernel<<<NBLK, TPB>>>(x, Wb, Wc, Wd, A, dp, (float*)d_out);
}

// round 13
// speedup vs baseline: 1.0887x; 1.0887x over previous
#include <cuda_runtime.h>

// Problem constants
#define TOK_TOTAL 4096      // B_SZ * L = 2 * 2048
#define Dm        1024
#define TPB       256
#define TOKS      2                       // tokens per block
#define NBLK      (TOK_TOTAL / TOKS)      // 2048 blocks
#define OUT_F4_PER_TOK 8196               // (2*1024+1)*16/4

__device__ __forceinline__ float softplus_f(float v) {
    // matches jax.nn.softplus = max(x,0) + log1p(exp(-|x|))
    return fmaxf(v, 0.0f) + log1pf(__expf(-fabsf(v)));
}

__global__ void __launch_bounds__(TPB, 5) ssm_fused_kernel(
    const float* __restrict__ x,
    const float* __restrict__ Wb,
    const float* __restrict__ Wc,
    const float* __restrict__ Wd,
    const float* __restrict__ A,
    const float* __restrict__ dp,
    float* __restrict__ out)
{
    // All shared arrays vector-typed: alignment guaranteed by the type system.
    __shared__ float4 s_x[TOKS][Dm / 4];   // 8 KB: 2 x rows
    __shared__ float2 s_dx[TOKS][Dm];      // 16 KB: (Delta, x) per (token, d)
    __shared__ float4 s_pj4[TOKS][9];      // [2][36] floats: B(0..15) C(16..31) sdel(32)

    float* s_pjf = (float*)s_pj4;          // row t at float offset t*36 (144 B, aligned)

    const int tid  = threadIdx.x;
    const int bt   = blockIdx.x;
    const int lane = tid & 31;
    const int w    = tid >> 5;

    const float4* A4 = (const float4*)A;

    // ---- Warm A's first lines into L1/L2 overlapped with the FMA prologue ----
    float4 a_pre = __ldg(A4 + tid);

    // ---- Stage 2 x rows (8 KB) ----
    const float4* x4 = (const float4*)x + (size_t)bt * (TOKS * Dm / 4);
    #pragma unroll
    for (int t = 0; t < TOKS; ++t)
        s_x[t][tid] = __ldg(x4 + t * 256 + tid);
    const float4 dpv = __ldg((const float4*)dp + tid);
    __syncthreads();

    // ---- Projections: 33 dots x 2 tokens. Warp w owns cols {w, w+8, ...} ----
    for (int c = w; c < 33; c += 8) {
        const float* Wrow = (c < 16) ? (Wb + c * Dm)
                          : (c < 32) ? (Wc + (c - 16) * Dm)
                          : Wd;
        const float4* W4 = (const float4*)Wrow;
        float acc0 = 0.0f, acc1 = 0.0f;
        #pragma unroll
        for (int k = 0; k < 8; ++k) {
            float4 wv = __ldg(W4 + lane + 32 * k);   // L1-resident across blocks
            float4 x0 = s_x[0][lane + 32 * k];
            float4 x1 = s_x[1][lane + 32 * k];
            acc0 = fmaf(x0.x, wv.x, acc0); acc1 = fmaf(x1.x, wv.x, acc1);
            acc0 = fmaf(x0.y, wv.y, acc0); acc1 = fmaf(x1.y, wv.y, acc1);
            acc0 = fmaf(x0.z, wv.z, acc0); acc1 = fmaf(x1.z, wv.z, acc1);
            acc0 = fmaf(x0.w, wv.w, acc0); acc1 = fmaf(x1.w, wv.w, acc1);
        }
        #pragma unroll
        for (int s = 16; s >= 1; s >>= 1) {
            acc0 += __shfl_xor_sync(0xffffffffu, acc0, s);
            acc1 += __shfl_xor_sync(0xffffffffu, acc1, s);
        }
        if (lane == 0) {
            s_pjf[0 * 36 + c] = acc0;
            s_pjf[1 * 36 + c] = acc1;
        }
    }
    __syncthreads();

    // ---- Softplus once per (token, d); pack (Delta, x) ----
    {
        const int d0 = tid * 4;
        #pragma unroll
        for (int t = 0; t < TOKS; ++t) {
            const float sdel = s_pjf[t * 36 + 32];
            const float4 xv  = s_x[t][tid];
            s_dx[t][d0 + 0] = make_float2(softplus_f(sdel + dpv.x), xv.x);
            s_dx[t][d0 + 1] = make_float2(softplus_f(sdel + dpv.y), xv.y);
            s_dx[t][d0 + 2] = make_float2(softplus_f(sdel + dpv.z), xv.z);
            s_dx[t][d0 + 3] = make_float2(softplus_f(sdel + dpv.w), xv.w);
        }
    }
    __syncthreads();

    float4* out4 = (float4*)out;
    float4* ob0 = out4 + (size_t)(bt * TOKS + 0) * OUT_F4_PER_TOK;
    float4* ob1 = out4 + (size_t)(bt * TOKS + 1) * OUT_F4_PER_TOK;
    const float4 Bq0 = s_pj4[0][tid & 3];   // per-thread invariant B quads
    const float4 Bq1 = s_pj4[1][tid & 3];

    // ---- Expansion: j outer, tokens inner. A loaded ONCE per j, 1/A shared. ----
    #pragma unroll 4
    for (int j = 0; j < 16; ++j) {
        const int f = tid + j * TPB;
        const int d = (tid >> 2) + j * 64;

        const float4 a = (j == 0) ? a_pre : __ldg(A4 + f);
        // One MUFU.RCP per element, shared by both tokens
        float4 ra;
        ra.x = __fdividef(1.0f, a.x);
        ra.y = __fdividef(1.0f, a.y);
        ra.z = __fdividef(1.0f, a.z);
        ra.w = __fdividef(1.0f, a.w);

        // --- token 0 ---
        {
            const float2 dx = s_dx[0][d];
            float4 ab;
            ab.x = __expf(dx.x * a.x);
            ab.y = __expf(dx.x * a.y);
            ab.z = __expf(dx.x * a.z);
            ab.w = __expf(dx.x * a.w);
            const float K0 = (Bq0.x * dx.y) * ra.x;
            const float K1 = (Bq0.y * dx.y) * ra.y;
            const float K2 = (Bq0.z * dx.y) * ra.z;
            const float K3 = (Bq0.w * dx.y) * ra.w;
            float4 o2;
            o2.x = fmaf(ab.x, K0, -K0);
            o2.y = fmaf(ab.y, K1, -K1);
            o2.z = fmaf(ab.z, K2, -K2);
            o2.w = fmaf(ab.w, K3, -K3);
            __stcs(ob0 + f, ab);
            __stcs(ob0 + 4096 + f, o2);
        }
        // --- token 1 ---
        {
            const float2 dx = s_dx[1][d];
            float4 ab;
            ab.x = __expf(dx.x * a.x);
            ab.y = __expf(dx.x * a.y);
            ab.z = __expf(dx.x * a.z);
            ab.w = __expf(dx.x * a.w);
            const float K0 = (Bq1.x * dx.y) * ra.x;
            const float K1 = (Bq1.y * dx.y) * ra.y;
            const float K2 = (Bq1.z * dx.y) * ra.z;
            const float K3 = (Bq1.w * dx.y) * ra.w;
            float4 o2;
            o2.x = fmaf(ab.x, K0, -K0);
            o2.y = fmaf(ab.y, K1, -K1);
            o2.z = fmaf(ab.z, K2, -K2);
            o2.w = fmaf(ab.w, K3, -K3);
            __stcs(ob1 + f, ab);
            __stcs(ob1 + 4096 + f, o2);
        }
    }

    // C rows: 16 floats at f4 offset 8192
    if (tid < 4) {
        __stcs(ob0 + 8192 + tid, s_pj4[0][4 + tid]);
        __stcs(ob1 + 8192 + tid, s_pj4[1][4 + tid]);
    }
}

extern "C" void kernel_launch(void* const* d_in, const int* in_sizes, int n_in,
                              void* d_out, int out_size)
{
    const float* x  = (const float*)d_in[0];
    const float* Wb = (const float*)d_in[1];
    const float* Wc = (const float*)d_in[2];
    const float* Wd = (const float*)d_in[3];
    const float* A  = (const float*)d_in[4];
    const float* dp = (const float*)d_in[5];

    ssm_fused_kernel<<<NBLK, TPB>>>(x, Wb, Wc, Wd, A, dp, (float*)d_out);
}